// round 1
// baseline (speedup 1.0000x reference)
#include <cuda_runtime.h>
#include <cuda_bf16.h>

#define NB  2
#define CC  512
#define THW 6272
#define CT  (CC*THW)                       // 3,211,264 per batch
#define EE  ((long long)THW*(long long)THW) // 39,337,984 per batch

// ---------------- device scratch (allocation-free rule: __device__ globals) ----------------
__device__ float g_WT[4][CC*CC];          // transposed weights Wh,Wg,Wm,Wz
__device__ float g_phx [NB*CT];
__device__ float g_pg  [NB*CT];
__device__ float g_phm [NB*CT];
__device__ float g_pm  [NB*CT];
__device__ float g_wz  [NB*CT];
__device__ float g_phmT[NB*CT];
__device__ float g_me  [NB*CT];
__device__ float g_energy[(size_t)NB*THW*THW];
__device__ float g_attT  [(size_t)NB*THW*THW];
__device__ float g_scale[CC];
__device__ float g_shift[CC];

// ---------------- TN GEMM: C[m,n] = sum_k A[k,m]*B[k,n] (+bias[m]) ----------------
// A: k-major, m contiguous (lda=M). B: k-major, n contiguous (ldb=N). C row-major (ldc=N).
// Requires M,N multiples of 128 and K multiple of 8 (true for all call sites).
__global__ void __launch_bounds__(256)
gemm_tn(const float* __restrict__ A, const float* __restrict__ B,
        float* __restrict__ C, const float* __restrict__ bias,
        int M, int Nn, int K, long long sA, long long sB, long long sC)
{
    __shared__ float As[8][128];
    __shared__ float Bs[8][128];
    const float* Ab = A + (long long)blockIdx.z * sA;
    const float* Bb = B + (long long)blockIdx.z * sB;
    float*       Cb = C + (long long)blockIdx.z * sC;

    const int m0 = blockIdx.y * 128;
    const int n0 = blockIdx.x * 128;
    const int tid = threadIdx.x;
    const int tx = tid & 15;          // 0..15 -> n micro
    const int ty = tid >> 4;          // 0..15 -> m micro
    const int lr = tid >> 5;          // 0..7  (k row for loads)
    const int lc = (tid & 31) << 2;   // 0..124 (float4 col)

    float acc[8][8];
#pragma unroll
    for (int i = 0; i < 8; i++)
#pragma unroll
        for (int j = 0; j < 8; j++) acc[i][j] = 0.f;

    for (int k0 = 0; k0 < K; k0 += 8) {
        float4 a4 = *reinterpret_cast<const float4*>(Ab + (long long)(k0 + lr) * M  + m0 + lc);
        float4 b4 = *reinterpret_cast<const float4*>(Bb + (long long)(k0 + lr) * Nn + n0 + lc);
        __syncthreads();
        *reinterpret_cast<float4*>(&As[lr][lc]) = a4;
        *reinterpret_cast<float4*>(&Bs[lr][lc]) = b4;
        __syncthreads();
#pragma unroll
        for (int kk = 0; kk < 8; kk++) {
            float a[8], b[8];
#pragma unroll
            for (int i = 0; i < 8; i++) a[i] = As[kk][ty * 8 + i];
#pragma unroll
            for (int j = 0; j < 8; j++) b[j] = Bs[kk][tx * 8 + j];
#pragma unroll
            for (int i = 0; i < 8; i++)
#pragma unroll
                for (int j = 0; j < 8; j++)
                    acc[i][j] = fmaf(a[i], b[j], acc[i][j]);
        }
    }

#pragma unroll
    for (int i = 0; i < 8; i++) {
        int m = m0 + ty * 8 + i;
        float bv = bias ? bias[m] : 0.f;
        float* cp = Cb + (long long)m * Nn + n0 + tx * 8;
#pragma unroll
        for (int j = 0; j < 8; j += 4) {
            float4 v = make_float4(acc[i][j] + bv, acc[i][j + 1] + bv,
                                   acc[i][j + 2] + bv, acc[i][j + 3] + bv);
            *reinterpret_cast<float4*>(cp + j) = v;
        }
    }
}

// ---------------- 32x32 tiled transpose: out[c*R + r] = in[r*Ccols + c] ----------------
__global__ void transpose_k(const float* __restrict__ in, float* __restrict__ out,
                            int R, int Ccols, long long sIn, long long sOut)
{
    __shared__ float tile[32][33];
    const float* ib = in  + (long long)blockIdx.z * sIn;
    float*       ob = out + (long long)blockIdx.z * sOut;
    int c0 = blockIdx.x * 32, r0 = blockIdx.y * 32;
    int x = threadIdx.x, y = threadIdx.y; // blockDim (32,8)
#pragma unroll
    for (int i = 0; i < 32; i += 8)
        tile[y + i][x] = ib[(long long)(r0 + y + i) * Ccols + c0 + x];
    __syncthreads();
#pragma unroll
    for (int i = 0; i < 32; i += 8)
        ob[(long long)(c0 + y + i) * R + r0 + x] = tile[x][y + i];
}

// ---------------- in-place row softmax (rowlen <= 25*256), 256 threads ----------------
__global__ void __launch_bounds__(256)
softmax_rows(float* __restrict__ data, int rowlen)
{
    float* p = data + (long long)blockIdx.x * rowlen;
    const int tid = threadIdx.x;
    __shared__ float red[8];

    float v[25];
    float mx = -3.0e38f;
#pragma unroll
    for (int i = 0; i < 25; i++) {
        int idx = tid + (i << 8);
        v[i] = (idx < rowlen) ? p[idx] : -3.0e38f;
        mx = fmaxf(mx, v[i]);
    }
#pragma unroll
    for (int o = 16; o; o >>= 1) mx = fmaxf(mx, __shfl_xor_sync(0xffffffffu, mx, o));
    if ((tid & 31) == 0) red[tid >> 5] = mx;
    __syncthreads();
    mx = red[0];
#pragma unroll
    for (int w = 1; w < 8; w++) mx = fmaxf(mx, red[w]);
    __syncthreads();

    float s = 0.f;
#pragma unroll
    for (int i = 0; i < 25; i++) {
        v[i] = __expf(v[i] - mx);   // OOB lanes: exp(-huge) == 0
        s += v[i];
    }
#pragma unroll
    for (int o = 16; o; o >>= 1) s += __shfl_xor_sync(0xffffffffu, s, o);
    if ((tid & 31) == 0) red[tid >> 5] = s;
    __syncthreads();
    s = 0.f;
#pragma unroll
    for (int w = 0; w < 8; w++) s += red[w];
    float inv = 1.f / s;

#pragma unroll
    for (int i = 0; i < 25; i++) {
        int idx = tid + (i << 8);
        if (idx < rowlen) p[idx] = v[i] * inv;
    }
}

// ---------------- BN batch stats per channel -> scale/shift ----------------
__global__ void __launch_bounds__(256)
bn_stats(const float* __restrict__ wz, const float* __restrict__ bn_w,
         const float* __restrict__ bn_b, float* __restrict__ scale,
         float* __restrict__ shift)
{
    int c = blockIdx.x;
    int tid = threadIdx.x;
    float s = 0.f, sq = 0.f;
    for (int i = tid; i < NB * THW; i += 256) {
        int n = i / THW, t = i - n * THW;
        float v = wz[(long long)n * CT + (long long)c * THW + t];
        s += v;
        sq = fmaf(v, v, sq);
    }
    __shared__ float r1[8], r2[8];
#pragma unroll
    for (int o = 16; o; o >>= 1) {
        s  += __shfl_xor_sync(0xffffffffu, s,  o);
        sq += __shfl_xor_sync(0xffffffffu, sq, o);
    }
    if ((tid & 31) == 0) { r1[tid >> 5] = s; r2[tid >> 5] = sq; }
    __syncthreads();
    if (tid == 0) {
        s = 0.f; sq = 0.f;
#pragma unroll
        for (int w = 0; w < 8; w++) { s += r1[w]; sq += r2[w]; }
        const float invn = 1.f / (float)(NB * THW);
        float mu  = s * invn;
        float var = sq * invn - mu * mu;
        float sc  = bn_w[c] * rsqrtf(var + 1e-5f);
        scale[c] = sc;
        shift[c] = bn_b[c] - mu * sc;
    }
}

// ---------------- final combine: out = gamma*pm*mask_atten + BN(wz) ----------------
__global__ void final_k(const float* __restrict__ pm, const float* __restrict__ ma,
                        const float* __restrict__ wz, const float* __restrict__ scale,
                        const float* __restrict__ shift, const float* __restrict__ gamma,
                        float* __restrict__ out)
{
    long long i = (long long)blockIdx.x * blockDim.x + threadIdx.x;
    if (i >= (long long)NB * CT) return;
    int c = (int)((i / THW) % CC);
    out[i] = gamma[0] * pm[i] * ma[i] + fmaf(wz[i], scale[c], shift[c]);
}

// ---------------- launch ----------------
extern "C" void kernel_launch(void* const* d_in, const int* in_sizes, int n_in,
                              void* d_out, int out_size)
{
    const float* x    = (const float*)d_in[0];
    const float* mask = (const float*)d_in[1];
    const float* Wh   = (const float*)d_in[2];
    const float* bh   = (const float*)d_in[3];
    const float* Wg   = (const float*)d_in[4];
    const float* bg   = (const float*)d_in[5];
    const float* Wm   = (const float*)d_in[6];
    const float* bm   = (const float*)d_in[7];
    const float* Wz   = (const float*)d_in[8];
    const float* bz   = (const float*)d_in[9];
    const float* bn_w = (const float*)d_in[10];
    const float* bn_b = (const float*)d_in[11];
    const float* gamma= (const float*)d_in[12];
    float* out = (float*)d_out;

    float *WT, *phx, *pg, *phm, *pm, *wz, *phmT, *me, *energy, *attT, *scale, *shift;
    cudaGetSymbolAddress((void**)&WT,    g_WT);
    cudaGetSymbolAddress((void**)&phx,   g_phx);
    cudaGetSymbolAddress((void**)&pg,    g_pg);
    cudaGetSymbolAddress((void**)&phm,   g_phm);
    cudaGetSymbolAddress((void**)&pm,    g_pm);
    cudaGetSymbolAddress((void**)&wz,    g_wz);
    cudaGetSymbolAddress((void**)&phmT,  g_phmT);
    cudaGetSymbolAddress((void**)&me,    g_me);
    cudaGetSymbolAddress((void**)&energy,g_energy);
    cudaGetSymbolAddress((void**)&attT,  g_attT);
    cudaGetSymbolAddress((void**)&scale, g_scale);
    cudaGetSymbolAddress((void**)&shift, g_shift);

    const dim3 t32(32, 8);

    // transpose the four 512x512 weights: WT[c*512+o] = W[o*512+c]
    transpose_k<<<dim3(16, 16, 1), t32>>>(Wh, WT + 0 * CC * CC, CC, CC, 0, 0);
    transpose_k<<<dim3(16, 16, 1), t32>>>(Wg, WT + 1 * CC * CC, CC, CC, 0, 0);
    transpose_k<<<dim3(16, 16, 1), t32>>>(Wm, WT + 2 * CC * CC, CC, CC, 0, 0);
    transpose_k<<<dim3(16, 16, 1), t32>>>(Wz, WT + 3 * CC * CC, CC, CC, 0, 0);

    // 1x1-conv projections: C[o,t] = sum_c WT[c,o] * X[c,t] + b[o]
    const dim3 gproj(THW / 128, CC / 128, NB);   // 49 x 4 x 2
    gemm_tn<<<gproj, 256>>>(WT + 0 * CC * CC, x,    phx, bh, CC, THW, CC, 0, CT, CT);
    gemm_tn<<<gproj, 256>>>(WT + 1 * CC * CC, x,    pg,  bg, CC, THW, CC, 0, CT, CT);
    gemm_tn<<<gproj, 256>>>(WT + 0 * CC * CC, mask, phm, bh, CC, THW, CC, 0, CT, CT);
    gemm_tn<<<gproj, 256>>>(WT + 2 * CC * CC, x,    pm,  bm, CC, THW, CC, 0, CT, CT);
    gemm_tn<<<gproj, 256>>>(WT + 3 * CC * CC, x,    wz,  bz, CC, THW, CC, 0, CT, CT);

    // energy[t,s] = sum_c phx[c,t] * pg[c,s]
    gemm_tn<<<dim3(THW / 128, THW / 128, NB), 256>>>(phx, pg, energy, nullptr,
                                                     THW, THW, CC, CT, CT, EE);
    // attention = softmax over s (in place)
    softmax_rows<<<NB * THW, 256>>>(energy, THW);

    // attT[s,t] = att[t,s]; phmT[s,c] = phm[c,s]
    transpose_k<<<dim3(THW / 32, THW / 32, NB), t32>>>(energy, attT, THW, THW, EE, EE);
    transpose_k<<<dim3(THW / 32, CC / 32,  NB), t32>>>(phm, phmT, CC, THW, CT, CT);

    // mask_energy[c,t] = sum_s phmT[s,c] * attT[s,t]
    gemm_tn<<<dim3(THW / 128, CC / 128, NB), 256>>>(phmT, attT, me, nullptr,
                                                    CC, THW, THW, CT, EE, CT);
    // mask_atten = softmax over t (in place)
    softmax_rows<<<NB * CC, 256>>>(me, THW);

    // BN stats on wz
    bn_stats<<<CC, 256>>>(wz, bn_w, bn_b, scale, shift);

    // out = gamma * pm * mask_atten + wz*scale + shift
    final_k<<<(NB * CT + 255) / 256, 256>>>(pm, me, wz, scale, shift, gamma, out);
}

// round 3
// speedup vs baseline: 5.5349x; 5.5349x over previous
#include <cuda_runtime.h>
#include <cuda_bf16.h>
#include <cstdint>

#define NB  2
#define CC  512
#define THW 6272
#define CT  (CC*THW)
#define EEL ((size_t)THW*(size_t)THW)

// ---------------- device scratch ----------------
__device__ float g_WT[CC*CC];                    // WzT fp32
__device__ float g_wz[NB*CT];                    // fp32 Wz projection
__device__ float g_me[NB*CT];                    // mask_energy fp32 (softmax in place)
__device__ float g_energy[NB*EEL];               // energy fp32
__device__ __nv_bfloat16 g_att  [NB*EEL];        // attention bf16 [t,s]
__device__ __nv_bfloat16 g_xT   [NB*CT];         // x^T   [t,c] bf16
__device__ __nv_bfloat16 g_maskT[NB*CT];         // mask^T[t,c] bf16
__device__ __nv_bfloat16 g_Wb   [3][CC*CC];      // Wh,Wg,Wm bf16 [o,c]
__device__ __nv_bfloat16 g_phxT [NB*CT];         // [t,c]
__device__ __nv_bfloat16 g_pgT  [NB*CT];         // [s,c]
__device__ __nv_bfloat16 g_phm  [NB*CT];         // [c,s]
__device__ __nv_bfloat16 g_pm   [NB*CT];         // [c,t]
__device__ float g_scale[CC];
__device__ float g_shift[CC];

// ---------------- helpers ----------------
__device__ __forceinline__ uint32_t smem_u32(const void* p) {
    uint32_t a;
    asm("{ .reg .u64 t; cvta.to.shared.u64 t, %1; cvt.u32.u64 %0, t; }" : "=r"(a) : "l"(p));
    return a;
}
#define SWZ128(o) ((o) ^ (((o) >> 3) & 0x70))
__device__ __forceinline__ void cp16(uint32_t s, const void* g) {
    asm volatile("cp.async.cg.shared.global [%0], [%1], 16;" :: "r"(s), "l"(g));
}
#define CP_COMMIT() asm volatile("cp.async.commit_group;" ::: "memory")
#define CP_WAIT(n)  asm volatile("cp.async.wait_group %0;" :: "n"(n) : "memory")

__device__ __forceinline__ void ldmx4(uint32_t& r0, uint32_t& r1, uint32_t& r2, uint32_t& r3,
                                      uint32_t addr) {
    asm volatile("ldmatrix.sync.aligned.m8n8.x4.shared.b16 {%0,%1,%2,%3}, [%4];"
                 : "=r"(r0), "=r"(r1), "=r"(r2), "=r"(r3) : "r"(addr));
}
__device__ __forceinline__ void mma16816(float* d, const uint32_t* a, const uint32_t* b) {
    asm volatile("mma.sync.aligned.m16n8k16.row.col.f32.bf16.bf16.f32 "
                 "{%0,%1,%2,%3}, {%4,%5,%6,%7}, {%8,%9}, {%0,%1,%2,%3};"
                 : "+f"(d[0]), "+f"(d[1]), "+f"(d[2]), "+f"(d[3])
                 : "r"(a[0]), "r"(a[1]), "r"(a[2]), "r"(a[3]), "r"(b[0]), "r"(b[1]));
}

// ---------------- HMMA bf16 TN GEMM: C[m,n] = sum_k A[m,k]*B[n,k] ----------------
// A: [M,K] bf16 row-major. B: [N,K] bf16 row-major. M,N mult of 128, K mult of 64.
// 256 threads, CTA tile 128x128, warp tile 64x32, K-chunk 64, 3-stage cp.async.
#define STAGES 3
__global__ void __launch_bounds__(256)
gemm_bf16_mma(const __nv_bfloat16* __restrict__ A, const __nv_bfloat16* __restrict__ B,
              void* __restrict__ Cv, int out_bf16,
              const float* __restrict__ bias_m, const float* __restrict__ bias_n,
              int M, int N, int K, long long sA, long long sB, long long sC)
{
    extern __shared__ char smem[];
    const uint32_t sb = smem_u32(smem);
    const int tid = threadIdx.x, wid = tid >> 5, lane = tid & 31;
    const int wm = wid & 1, wn = wid >> 1;          // warp grid 2 (m) x 4 (n)
    const int m_w = wm * 64, n_w = wn * 32;

    // per-stage: A 128x64 bf16 (16KB) + B 128x64 bf16 (16KB)
    uint32_t bufA[STAGES], bufB[STAGES];
#pragma unroll
    for (int s = 0; s < STAGES; s++) { bufA[s] = sb + s * 32768; bufB[s] = sb + s * 32768 + 16384; }

    const int m0 = blockIdx.y * 128, n0 = blockIdx.x * 128;
    const char* Ab = (const char*)(A + (long long)blockIdx.z * sA + (long long)m0 * K);
    const char* Bb = (const char*)(B + (long long)blockIdx.z * sB + (long long)n0 * K);
    const long long rowBytes = (long long)K * 2;
    const int nc = K >> 6;

    auto load_chunk = [&](int c, int s) {
        const char* ga = Ab + (long long)c * 128;
        const char* gb = Bb + (long long)c * 128;
#pragma unroll
        for (int i = 0; i < 4; i++) {
            int seg = tid + i * 256;
            int row = seg >> 3;
            int col = (seg & 7) << 4;
            uint32_t off = SWZ128((uint32_t)(row * 128 + col));
            long long goff = (long long)row * rowBytes + col;
            cp16(bufA[s] + off, ga + goff);
            cp16(bufB[s] + off, gb + goff);
        }
    };

    float acc[4][4][4];
#pragma unroll
    for (int i = 0; i < 4; i++)
#pragma unroll
        for (int j = 0; j < 4; j++)
#pragma unroll
            for (int q = 0; q < 4; q++) acc[i][j][q] = 0.f;

    // ldmatrix lane-address precompute
    const int grp = lane >> 3, rw = lane & 7;
    // A x4: mat0 rows m+0..7 kLo, mat1 rows m+8..15 kLo, mat2 m+0..7 kHi, mat3 m+8..15 kHi
    const int a_row = (grp & 1) * 8 + rw;
    const int a_kh  = (grp >> 1) * 16;
    // B x4 (2 n-tiles): mat0 n+0..7 kLo, mat1 n+0..7 kHi, mat2 n+8..15 kLo, mat3 n+8..15 kHi
    const int b_row = (grp >> 1) * 8 + rw;
    const int b_kh  = (grp & 1) * 16;

    load_chunk(0, 0); CP_COMMIT();
    if (nc > 1) { load_chunk(1, 1); CP_COMMIT(); }

    for (int c = 0; c < nc; c++) {
        if (c + 1 < nc) { CP_WAIT(1); } else { CP_WAIT(0); }
        __syncthreads();
        const uint32_t sa = bufA[c % STAGES], sbm = bufB[c % STAGES];
#pragma unroll
        for (int kk = 0; kk < 4; kk++) {
            const int kb = kk * 32;
            uint32_t a[4][4], b[4][2];
#pragma unroll
            for (int mt = 0; mt < 4; mt++) {
                int row = m_w + mt * 16 + a_row;
                uint32_t ad = sa + SWZ128((uint32_t)(row * 128 + kb + a_kh));
                ldmx4(a[mt][0], a[mt][1], a[mt][2], a[mt][3], ad);
            }
#pragma unroll
            for (int np = 0; np < 2; np++) {
                int row = n_w + np * 16 + b_row;
                uint32_t bd = sbm + SWZ128((uint32_t)(row * 128 + kb + b_kh));
                uint32_t r0, r1, r2, r3;
                ldmx4(r0, r1, r2, r3, bd);
                b[np * 2][0] = r0; b[np * 2][1] = r1;
                b[np * 2 + 1][0] = r2; b[np * 2 + 1][1] = r3;
            }
#pragma unroll
            for (int mt = 0; mt < 4; mt++)
#pragma unroll
                for (int nt = 0; nt < 4; nt++)
                    mma16816(acc[mt][nt], a[mt], b[nt]);
        }
        __syncthreads();
        if (c + 2 < nc) { load_chunk(c + 2, (c + 2) % STAGES); CP_COMMIT(); }
    }

    // epilogue
    const int r_lo = lane >> 2, c_off = (lane & 3) * 2;
#pragma unroll
    for (int mt = 0; mt < 4; mt++) {
        int row = m0 + m_w + mt * 16 + r_lo;
#pragma unroll
        for (int half = 0; half < 2; half++) {
            int r = row + half * 8;
            float bmv = bias_m ? bias_m[r] : 0.f;
            long long base = (long long)blockIdx.z * sC + (long long)r * N + n0 + n_w + c_off;
#pragma unroll
            for (int nt = 0; nt < 4; nt++) {
                float v0 = acc[mt][nt][half * 2 + 0] + bmv;
                float v1 = acc[mt][nt][half * 2 + 1] + bmv;
                int col = n0 + n_w + nt * 8 + c_off;
                if (bias_n) { v0 += bias_n[col]; v1 += bias_n[col + 1]; }
                if (out_bf16) {
                    __nv_bfloat162 h2 = __floats2bfloat162_rn(v0, v1);
                    *reinterpret_cast<__nv_bfloat162*>((__nv_bfloat16*)Cv + base + nt * 8) = h2;
                } else {
                    *reinterpret_cast<float2*>((float*)Cv + base + nt * 8) = make_float2(v0, v1);
                }
            }
        }
    }
}

// ---------------- fp32 SIMT TN GEMM (Wz branch only) ----------------
__global__ void __launch_bounds__(256)
gemm_tn(const float* __restrict__ A, const float* __restrict__ B,
        float* __restrict__ C, const float* __restrict__ bias,
        int M, int Nn, int K, long long sA, long long sB, long long sC)
{
    __shared__ float As[8][128];
    __shared__ float Bs[8][128];
    const float* Ab = A + (long long)blockIdx.z * sA;
    const float* Bb = B + (long long)blockIdx.z * sB;
    float*       Cb = C + (long long)blockIdx.z * sC;

    const int m0 = blockIdx.y * 128, n0 = blockIdx.x * 128;
    const int tid = threadIdx.x;
    const int tx = tid & 15, ty = tid >> 4;
    const int lr = tid >> 5, lc = (tid & 31) << 2;

    float acc[8][8];
#pragma unroll
    for (int i = 0; i < 8; i++)
#pragma unroll
        for (int j = 0; j < 8; j++) acc[i][j] = 0.f;

    for (int k0 = 0; k0 < K; k0 += 8) {
        float4 a4 = *reinterpret_cast<const float4*>(Ab + (long long)(k0 + lr) * M  + m0 + lc);
        float4 b4 = *reinterpret_cast<const float4*>(Bb + (long long)(k0 + lr) * Nn + n0 + lc);
        __syncthreads();
        *reinterpret_cast<float4*>(&As[lr][lc]) = a4;
        *reinterpret_cast<float4*>(&Bs[lr][lc]) = b4;
        __syncthreads();
#pragma unroll
        for (int kk = 0; kk < 8; kk++) {
            float a[8], b[8];
#pragma unroll
            for (int i = 0; i < 8; i++) a[i] = As[kk][ty * 8 + i];
#pragma unroll
            for (int j = 0; j < 8; j++) b[j] = Bs[kk][tx * 8 + j];
#pragma unroll
            for (int i = 0; i < 8; i++)
#pragma unroll
                for (int j = 0; j < 8; j++)
                    acc[i][j] = fmaf(a[i], b[j], acc[i][j]);
        }
    }
#pragma unroll
    for (int i = 0; i < 8; i++) {
        int m = m0 + ty * 8 + i;
        float bv = bias ? bias[m] : 0.f;
        float* cp = Cb + (long long)m * Nn + n0 + tx * 8;
#pragma unroll
        for (int j = 0; j < 8; j += 4) {
            float4 v = make_float4(acc[i][j] + bv, acc[i][j + 1] + bv,
                                   acc[i][j + 2] + bv, acc[i][j + 3] + bv);
            *reinterpret_cast<float4*>(cp + j) = v;
        }
    }
}

// ---------------- fp32 transpose (for WzT) ----------------
__global__ void transpose_k(const float* __restrict__ in, float* __restrict__ out,
                            int R, int Ccols, long long sIn, long long sOut)
{
    __shared__ float tile[32][33];
    const float* ib = in  + (long long)blockIdx.z * sIn;
    float*       ob = out + (long long)blockIdx.z * sOut;
    int c0 = blockIdx.x * 32, r0 = blockIdx.y * 32;
    int x = threadIdx.x, y = threadIdx.y;
#pragma unroll
    for (int i = 0; i < 32; i += 8)
        tile[y + i][x] = ib[(long long)(r0 + y + i) * Ccols + c0 + x];
    __syncthreads();
#pragma unroll
    for (int i = 0; i < 32; i += 8)
        ob[(long long)(c0 + y + i) * R + r0 + x] = tile[x][y + i];
}

// ---------------- transpose + fp32->bf16 ----------------
__global__ void transpose_cvt(const float* __restrict__ in, __nv_bfloat16* __restrict__ out,
                              int R, int Ccols, long long sIn, long long sOut)
{
    __shared__ float tile[32][33];
    const float* ib = in + (long long)blockIdx.z * sIn;
    __nv_bfloat16* ob = out + (long long)blockIdx.z * sOut;
    int c0 = blockIdx.x * 32, r0 = blockIdx.y * 32;
    int x = threadIdx.x, y = threadIdx.y;
#pragma unroll
    for (int i = 0; i < 32; i += 8)
        tile[y + i][x] = ib[(long long)(r0 + y + i) * Ccols + c0 + x];
    __syncthreads();
#pragma unroll
    for (int i = 0; i < 32; i += 8)
        ob[(long long)(c0 + y + i) * R + r0 + x] = __float2bfloat16(tile[x][y + i]);
}

// ---------------- fp32 -> bf16 convert ----------------
__global__ void cvt_bf16(const float* __restrict__ in, __nv_bfloat16* __restrict__ out, int n)
{
    int i = blockIdx.x * blockDim.x + threadIdx.x;
    if (i < n) out[i] = __float2bfloat16(in[i]);
}

// ---------------- softmax (fp32 in, bf16 out) ----------------
__global__ void __launch_bounds__(256)
softmax_bf16(const float* __restrict__ in, __nv_bfloat16* __restrict__ out, int rowlen)
{
    const float* p = in + (long long)blockIdx.x * rowlen;
    __nv_bfloat16* q = out + (long long)blockIdx.x * rowlen;
    const int tid = threadIdx.x;
    __shared__ float red[8];

    float v[25];
    float mx = -3.0e38f;
#pragma unroll
    for (int i = 0; i < 25; i++) {
        int idx = tid + (i << 8);
        v[i] = (idx < rowlen) ? p[idx] : -3.0e38f;
        mx = fmaxf(mx, v[i]);
    }
#pragma unroll
    for (int o = 16; o; o >>= 1) mx = fmaxf(mx, __shfl_xor_sync(0xffffffffu, mx, o));
    if ((tid & 31) == 0) red[tid >> 5] = mx;
    __syncthreads();
    mx = red[0];
#pragma unroll
    for (int w = 1; w < 8; w++) mx = fmaxf(mx, red[w]);
    __syncthreads();

    float s = 0.f;
#pragma unroll
    for (int i = 0; i < 25; i++) { v[i] = __expf(v[i] - mx); s += v[i]; }
#pragma unroll
    for (int o = 16; o; o >>= 1) s += __shfl_xor_sync(0xffffffffu, s, o);
    if ((tid & 31) == 0) red[tid >> 5] = s;
    __syncthreads();
    s = 0.f;
#pragma unroll
    for (int w = 0; w < 8; w++) s += red[w];
    float inv = 1.f / s;
#pragma unroll
    for (int i = 0; i < 25; i++) {
        int idx = tid + (i << 8);
        if (idx < rowlen) q[idx] = __float2bfloat16(v[i] * inv);
    }
}

// ---------------- softmax fp32 in-place ----------------
__global__ void __launch_bounds__(256)
softmax_rows(float* __restrict__ data, int rowlen)
{
    float* p = data + (long long)blockIdx.x * rowlen;
    const int tid = threadIdx.x;
    __shared__ float red[8];

    float v[25];
    float mx = -3.0e38f;
#pragma unroll
    for (int i = 0; i < 25; i++) {
        int idx = tid + (i << 8);
        v[i] = (idx < rowlen) ? p[idx] : -3.0e38f;
        mx = fmaxf(mx, v[i]);
    }
#pragma unroll
    for (int o = 16; o; o >>= 1) mx = fmaxf(mx, __shfl_xor_sync(0xffffffffu, mx, o));
    if ((tid & 31) == 0) red[tid >> 5] = mx;
    __syncthreads();
    mx = red[0];
#pragma unroll
    for (int w = 1; w < 8; w++) mx = fmaxf(mx, red[w]);
    __syncthreads();

    float s = 0.f;
#pragma unroll
    for (int i = 0; i < 25; i++) { v[i] = __expf(v[i] - mx); s += v[i]; }
#pragma unroll
    for (int o = 16; o; o >>= 1) s += __shfl_xor_sync(0xffffffffu, s, o);
    if ((tid & 31) == 0) red[tid >> 5] = s;
    __syncthreads();
    s = 0.f;
#pragma unroll
    for (int w = 0; w < 8; w++) s += red[w];
    float inv = 1.f / s;
#pragma unroll
    for (int i = 0; i < 25; i++) {
        int idx = tid + (i << 8);
        if (idx < rowlen) p[idx] = v[i] * inv;
    }
}

// ---------------- BN stats ----------------
__global__ void __launch_bounds__(256)
bn_stats(const float* __restrict__ wz, const float* __restrict__ bn_w,
         const float* __restrict__ bn_b, float* __restrict__ scale,
         float* __restrict__ shift)
{
    int c = blockIdx.x;
    int tid = threadIdx.x;
    float s = 0.f, sq = 0.f;
    for (int i = tid; i < NB * THW; i += 256) {
        int n = i / THW, t = i - n * THW;
        float v = wz[(long long)n * CT + (long long)c * THW + t];
        s += v;
        sq = fmaf(v, v, sq);
    }
    __shared__ float r1[8], r2[8];
#pragma unroll
    for (int o = 16; o; o >>= 1) {
        s  += __shfl_xor_sync(0xffffffffu, s,  o);
        sq += __shfl_xor_sync(0xffffffffu, sq, o);
    }
    if ((tid & 31) == 0) { r1[tid >> 5] = s; r2[tid >> 5] = sq; }
    __syncthreads();
    if (tid == 0) {
        s = 0.f; sq = 0.f;
#pragma unroll
        for (int w = 0; w < 8; w++) { s += r1[w]; sq += r2[w]; }
        const float invn = 1.f / (float)(NB * THW);
        float mu  = s * invn;
        float var = sq * invn - mu * mu;
        float sc  = bn_w[c] * rsqrtf(var + 1e-5f);
        scale[c] = sc;
        shift[c] = bn_b[c] - mu * sc;
    }
}

// ---------------- final combine ----------------
__global__ void final_k(const __nv_bfloat16* __restrict__ pm, const float* __restrict__ ma,
                        const float* __restrict__ wz, const float* __restrict__ scale,
                        const float* __restrict__ shift, const float* __restrict__ gamma,
                        float* __restrict__ out)
{
    long long i = (long long)blockIdx.x * blockDim.x + threadIdx.x;
    if (i >= (long long)NB * CT) return;
    int c = (int)((i / THW) % CC);
    out[i] = gamma[0] * __bfloat162float(pm[i]) * ma[i] + fmaf(wz[i], scale[c], shift[c]);
}

// ---------------- launch ----------------
extern "C" void kernel_launch(void* const* d_in, const int* in_sizes, int n_in,
                              void* d_out, int out_size)
{
    const float* x    = (const float*)d_in[0];
    const float* mask = (const float*)d_in[1];
    const float* Wh   = (const float*)d_in[2];
    const float* bh   = (const float*)d_in[3];
    const float* Wg   = (const float*)d_in[4];
    const float* bg   = (const float*)d_in[5];
    const float* Wm   = (const float*)d_in[6];
    const float* bm   = (const float*)d_in[7];
    const float* Wz   = (const float*)d_in[8];
    const float* bz   = (const float*)d_in[9];
    const float* bn_w = (const float*)d_in[10];
    const float* bn_b = (const float*)d_in[11];
    const float* gamma= (const float*)d_in[12];
    float* out = (float*)d_out;

    float *WT, *wz, *me, *energy, *scale, *shift;
    __nv_bfloat16 *att, *xT, *maskT, *Wb, *phxT, *pgT, *phm, *pm;
    cudaGetSymbolAddress((void**)&WT,     g_WT);
    cudaGetSymbolAddress((void**)&wz,     g_wz);
    cudaGetSymbolAddress((void**)&me,     g_me);
    cudaGetSymbolAddress((void**)&energy, g_energy);
    cudaGetSymbolAddress((void**)&att,    g_att);
    cudaGetSymbolAddress((void**)&xT,     g_xT);
    cudaGetSymbolAddress((void**)&maskT,  g_maskT);
    cudaGetSymbolAddress((void**)&Wb,     g_Wb);
    cudaGetSymbolAddress((void**)&phxT,   g_phxT);
    cudaGetSymbolAddress((void**)&pgT,    g_pgT);
    cudaGetSymbolAddress((void**)&phm,    g_phm);
    cudaGetSymbolAddress((void**)&pm,     g_pm);
    cudaGetSymbolAddress((void**)&scale,  g_scale);
    cudaGetSymbolAddress((void**)&shift,  g_shift);

    const long long EE = (long long)EEL;
    const int SMEM_GEMM = STAGES * 32768;   // 96KB
    cudaFuncSetAttribute(gemm_bf16_mma, cudaFuncAttributeMaxDynamicSharedMemorySize, SMEM_GEMM);

    const dim3 t32(32, 8);

    // weight conversions / transposes
    cvt_bf16<<<(CC * CC + 255) / 256, 256>>>(Wh, Wb + 0 * CC * CC, CC * CC);
    cvt_bf16<<<(CC * CC + 255) / 256, 256>>>(Wg, Wb + 1 * CC * CC, CC * CC);
    cvt_bf16<<<(CC * CC + 255) / 256, 256>>>(Wm, Wb + 2 * CC * CC, CC * CC);
    transpose_k<<<dim3(16, 16, 1), t32>>>(Wz, WT, CC, CC, 0, 0);

    // x^T, mask^T (bf16)
    transpose_cvt<<<dim3(THW / 32, CC / 32, NB), t32>>>(x,    xT,    CC, THW, CT, CT);
    transpose_cvt<<<dim3(THW / 32, CC / 32, NB), t32>>>(mask, maskT, CC, THW, CT, CT);

    // projections on tensor cores (bf16 out)
    // phxT[t,o] = sum_c xT[t,c]*Wh[o,c] + bh[o]
    gemm_bf16_mma<<<dim3(CC / 128, THW / 128, NB), 256, SMEM_GEMM>>>(
        xT, Wb + 0 * CC * CC, phxT, 1, nullptr, bh, THW, CC, CC, CT, 0, CT);
    gemm_bf16_mma<<<dim3(CC / 128, THW / 128, NB), 256, SMEM_GEMM>>>(
        xT, Wb + 1 * CC * CC, pgT, 1, nullptr, bg, THW, CC, CC, CT, 0, CT);
    // phm[o,s] = sum_c Wh[o,c]*maskT[s,c] + bh[o]
    gemm_bf16_mma<<<dim3(THW / 128, CC / 128, NB), 256, SMEM_GEMM>>>(
        Wb + 0 * CC * CC, maskT, phm, 1, bh, nullptr, CC, THW, CC, 0, CT, CT);
    // pm[o,t] = sum_c Wm[o,c]*xT[t,c] + bm[o]
    gemm_bf16_mma<<<dim3(THW / 128, CC / 128, NB), 256, SMEM_GEMM>>>(
        Wb + 2 * CC * CC, xT, pm, 1, bm, nullptr, CC, THW, CC, 0, CT, CT);

    // wz (fp32 accurate branch): wz[o,t] = sum_c WzT[c,o]*x[c,t] + bz[o]
    gemm_tn<<<dim3(THW / 128, CC / 128, NB), 256>>>(WT, x, wz, bz, CC, THW, CC, 0, CT, CT);

    // energy[t,s] = sum_c phxT[t,c]*pgT[s,c]   (fp32 out)
    gemm_bf16_mma<<<dim3(THW / 128, THW / 128, NB), 256, SMEM_GEMM>>>(
        phxT, pgT, energy, 0, nullptr, nullptr, THW, THW, CC, CT, CT, EE);

    // attention = softmax_s(energy) -> bf16
    softmax_bf16<<<NB * THW, 256>>>(energy, att, THW);

    // mask_energy[c,t] = sum_s phm[c,s]*att[t,s]   (fp32 out)
    gemm_bf16_mma<<<dim3(THW / 128, CC / 128, NB), 256, SMEM_GEMM>>>(
        phm, att, me, 0, nullptr, nullptr, CC, THW, THW, CT, EE, CT);

    // mask_atten = softmax_t(mask_energy), in place
    softmax_rows<<<NB * CC, 256>>>(me, THW);

    // BN stats on wz
    bn_stats<<<CC, 256>>>(wz, bn_w, bn_b, scale, shift);

    // out = gamma*pm*mask_atten + BN(wz)
    final_k<<<(NB * CT + 255) / 256, 256>>>(pm, me, wz, scale, shift, gamma, out);
}

// round 4
// speedup vs baseline: 6.4908x; 1.1727x over previous
#include <cuda_runtime.h>
#include <cuda_bf16.h>
#include <cstdint>

#define NB  2
#define CC  512
#define THW 6272
#define CT  (CC*THW)
#define EEL ((size_t)THW*(size_t)THW)
#define K3  (3*CC)                         // 1536

// ---------------- device scratch ----------------
__device__ float g_wz[NB*CT];                    // fp32 Wz projection [o,t]
__device__ float g_me[NB*CT];                    // mask_energy fp32 (softmax in place)
__device__ __nv_bfloat16 g_att  [NB*EEL];        // energy -> attention bf16 [t,s]
__device__ __nv_bfloat16 g_x3   [NB*(size_t)THW*K3]; // [t, x_hi|x_lo|x_hi]
__device__ __nv_bfloat16 g_Wz3  [CC*K3];         // [o, w_hi|w_hi|w_lo]
__device__ __nv_bfloat16 g_maskT[NB*CT];         // mask^T[t,c] bf16
__device__ __nv_bfloat16 g_Wb   [3][CC*CC];      // Wh,Wg,Wm bf16 [o,c]
__device__ __nv_bfloat16 g_phxT [NB*CT];         // [t,c]
__device__ __nv_bfloat16 g_pgT  [NB*CT];         // [s,c]
__device__ __nv_bfloat16 g_phm  [NB*CT];         // [c,s]
__device__ __nv_bfloat16 g_pm   [NB*CT];         // [c,t]
__device__ float g_scale[CC];
__device__ float g_shift[CC];

// ---------------- helpers ----------------
__device__ __forceinline__ uint32_t smem_u32(const void* p) {
    uint32_t a;
    asm("{ .reg .u64 t; cvta.to.shared.u64 t, %1; cvt.u32.u64 %0, t; }" : "=r"(a) : "l"(p));
    return a;
}
#define SWZ128(o) ((o) ^ (((o) >> 3) & 0x70))
__device__ __forceinline__ void cp16(uint32_t s, const void* g) {
    asm volatile("cp.async.cg.shared.global [%0], [%1], 16;" :: "r"(s), "l"(g));
}
#define CP_COMMIT() asm volatile("cp.async.commit_group;" ::: "memory")
#define CP_WAIT(n)  asm volatile("cp.async.wait_group %0;" :: "n"(n) : "memory")

__device__ __forceinline__ void ldmx4(uint32_t& r0, uint32_t& r1, uint32_t& r2, uint32_t& r3,
                                      uint32_t addr) {
    asm volatile("ldmatrix.sync.aligned.m8n8.x4.shared.b16 {%0,%1,%2,%3}, [%4];"
                 : "=r"(r0), "=r"(r1), "=r"(r2), "=r"(r3) : "r"(addr));
}
__device__ __forceinline__ void mma16816(float* d, const uint32_t* a, const uint32_t* b) {
    asm volatile("mma.sync.aligned.m16n8k16.row.col.f32.bf16.bf16.f32 "
                 "{%0,%1,%2,%3}, {%4,%5,%6,%7}, {%8,%9}, {%0,%1,%2,%3};"
                 : "+f"(d[0]), "+f"(d[1]), "+f"(d[2]), "+f"(d[3])
                 : "r"(a[0]), "r"(a[1]), "r"(a[2]), "r"(a[3]), "r"(b[0]), "r"(b[1]));
}

// ---------------- HMMA bf16 TN GEMM: C[m,n] = sum_k A[m,k]*B[n,k] ----------------
// A: [M,ldA] bf16 row-major (uses K cols). B: [N,ldB] bf16 row-major.
// M,N mult of 128, K mult of 64. 256 threads, CTA 128x128, warp 64x32, 3-stage.
#define STAGES 3
__global__ void __launch_bounds__(256)
gemm_bf16_mma(const __nv_bfloat16* __restrict__ A, const __nv_bfloat16* __restrict__ B,
              void* __restrict__ Cv, int out_bf16,
              const float* __restrict__ bias_m, const float* __restrict__ bias_n,
              int M, int N, int K, int ldA, int ldB,
              long long sA, long long sB, long long sC)
{
    extern __shared__ char smem[];
    const uint32_t sb = smem_u32(smem);
    const int tid = threadIdx.x, wid = tid >> 5, lane = tid & 31;
    const int wm = wid & 1, wn = wid >> 1;          // warp grid 2 (m) x 4 (n)
    const int m_w = wm * 64, n_w = wn * 32;

    uint32_t bufA[STAGES], bufB[STAGES];
#pragma unroll
    for (int s = 0; s < STAGES; s++) { bufA[s] = sb + s * 32768; bufB[s] = sb + s * 32768 + 16384; }

    const int m0 = blockIdx.y * 128, n0 = blockIdx.x * 128;
    const char* Ab = (const char*)(A + (long long)blockIdx.z * sA + (long long)m0 * ldA);
    const char* Bb = (const char*)(B + (long long)blockIdx.z * sB + (long long)n0 * ldB);
    const long long rbA = (long long)ldA * 2;
    const long long rbB = (long long)ldB * 2;
    const int nc = K >> 6;

    auto load_chunk = [&](int c, int s) {
        const char* ga = Ab + (long long)c * 128;
        const char* gb = Bb + (long long)c * 128;
#pragma unroll
        for (int i = 0; i < 4; i++) {
            int seg = tid + i * 256;
            int row = seg >> 3;
            int col = (seg & 7) << 4;
            uint32_t off = SWZ128((uint32_t)(row * 128 + col));
            cp16(bufA[s] + off, ga + (long long)row * rbA + col);
            cp16(bufB[s] + off, gb + (long long)row * rbB + col);
        }
    };

    float acc[4][4][4];
#pragma unroll
    for (int i = 0; i < 4; i++)
#pragma unroll
        for (int j = 0; j < 4; j++)
#pragma unroll
            for (int q = 0; q < 4; q++) acc[i][j][q] = 0.f;

    const int grp = lane >> 3, rw = lane & 7;
    const int a_row = (grp & 1) * 8 + rw;
    const int a_kh  = (grp >> 1) * 16;
    const int b_row = (grp >> 1) * 8 + rw;
    const int b_kh  = (grp & 1) * 16;

    load_chunk(0, 0); CP_COMMIT();
    if (nc > 1) { load_chunk(1, 1); CP_COMMIT(); }

    for (int c = 0; c < nc; c++) {
        if (c + 1 < nc) { CP_WAIT(1); } else { CP_WAIT(0); }
        __syncthreads();
        const uint32_t sa = bufA[c % STAGES], sbm = bufB[c % STAGES];
#pragma unroll
        for (int kk = 0; kk < 4; kk++) {
            const int kb = kk * 32;
            uint32_t a[4][4], b[4][2];
#pragma unroll
            for (int mt = 0; mt < 4; mt++) {
                int row = m_w + mt * 16 + a_row;
                uint32_t ad = sa + SWZ128((uint32_t)(row * 128 + kb + a_kh));
                ldmx4(a[mt][0], a[mt][1], a[mt][2], a[mt][3], ad);
            }
#pragma unroll
            for (int np = 0; np < 2; np++) {
                int row = n_w + np * 16 + b_row;
                uint32_t bd = sbm + SWZ128((uint32_t)(row * 128 + kb + b_kh));
                uint32_t r0, r1, r2, r3;
                ldmx4(r0, r1, r2, r3, bd);
                b[np * 2][0] = r0; b[np * 2][1] = r1;
                b[np * 2 + 1][0] = r2; b[np * 2 + 1][1] = r3;
            }
#pragma unroll
            for (int mt = 0; mt < 4; mt++)
#pragma unroll
                for (int nt = 0; nt < 4; nt++)
                    mma16816(acc[mt][nt], a[mt], b[nt]);
        }
        __syncthreads();
        if (c + 2 < nc) { load_chunk(c + 2, (c + 2) % STAGES); CP_COMMIT(); }
    }

    // epilogue
    const int r_lo = lane >> 2, c_off = (lane & 3) * 2;
#pragma unroll
    for (int mt = 0; mt < 4; mt++) {
        int row = m0 + m_w + mt * 16 + r_lo;
#pragma unroll
        for (int half = 0; half < 2; half++) {
            int r = row + half * 8;
            float bmv = bias_m ? bias_m[r] : 0.f;
            long long base = (long long)blockIdx.z * sC + (long long)r * N + n0 + n_w + c_off;
#pragma unroll
            for (int nt = 0; nt < 4; nt++) {
                float v0 = acc[mt][nt][half * 2 + 0] + bmv;
                float v1 = acc[mt][nt][half * 2 + 1] + bmv;
                int col = n0 + n_w + nt * 8 + c_off;
                if (bias_n) { v0 += bias_n[col]; v1 += bias_n[col + 1]; }
                if (out_bf16) {
                    __nv_bfloat162 h2 = __floats2bfloat162_rn(v0, v1);
                    *reinterpret_cast<__nv_bfloat162*>((__nv_bfloat16*)Cv + base + nt * 8) = h2;
                } else {
                    *reinterpret_cast<float2*>((float*)Cv + base + nt * 8) = make_float2(v0, v1);
                }
            }
        }
    }
}

// ---------------- transpose + hi/lo split: x [c,t] fp32 -> x3 [t, hi|lo|hi] ----------------
__global__ void split_x(const float* __restrict__ in, __nv_bfloat16* __restrict__ out,
                        long long sIn, long long sOut)
{
    __shared__ float tile[32][33];
    const float* ib = in + (long long)blockIdx.z * sIn;
    __nv_bfloat16* ob = out + (long long)blockIdx.z * sOut;
    int t0 = blockIdx.x * 32, c0 = blockIdx.y * 32;
    int x = threadIdx.x, y = threadIdx.y;
#pragma unroll
    for (int i = 0; i < 32; i += 8)
        tile[y + i][x] = ib[(long long)(c0 + y + i) * THW + t0 + x];
    __syncthreads();
#pragma unroll
    for (int i = 0; i < 32; i += 8) {
        float v = tile[x][y + i];
        __nv_bfloat16 hi = __float2bfloat16(v);
        __nv_bfloat16 lo = __float2bfloat16(v - __bfloat162float(hi));
        long long row = (long long)(t0 + y + i) * K3;
        ob[row + c0 + x]            = hi;
        ob[row + CC + c0 + x]       = lo;
        ob[row + 2 * CC + c0 + x]   = hi;
    }
}

// ---------------- Wz [o,c] fp32 -> Wz3 [o, hi|hi|lo] ----------------
__global__ void split_w(const float* __restrict__ in, __nv_bfloat16* __restrict__ out)
{
    int i = blockIdx.x * blockDim.x + threadIdx.x;
    if (i >= CC * CC) return;
    int o = i / CC, c = i - o * CC;
    float v = in[i];
    __nv_bfloat16 hi = __float2bfloat16(v);
    __nv_bfloat16 lo = __float2bfloat16(v - __bfloat162float(hi));
    out[(long long)o * K3 + c]          = hi;
    out[(long long)o * K3 + CC + c]     = hi;
    out[(long long)o * K3 + 2 * CC + c] = lo;
}

// ---------------- transpose + fp32->bf16 (mask^T) ----------------
__global__ void transpose_cvt(const float* __restrict__ in, __nv_bfloat16* __restrict__ out,
                              int R, int Ccols, long long sIn, long long sOut)
{
    __shared__ float tile[32][33];
    const float* ib = in + (long long)blockIdx.z * sIn;
    __nv_bfloat16* ob = out + (long long)blockIdx.z * sOut;
    int c0 = blockIdx.x * 32, r0 = blockIdx.y * 32;
    int x = threadIdx.x, y = threadIdx.y;
#pragma unroll
    for (int i = 0; i < 32; i += 8)
        tile[y + i][x] = ib[(long long)(r0 + y + i) * Ccols + c0 + x];
    __syncthreads();
#pragma unroll
    for (int i = 0; i < 32; i += 8)
        ob[(long long)(c0 + y + i) * R + r0 + x] = __float2bfloat16(tile[x][y + i]);
}

// ---------------- fp32 -> bf16 convert ----------------
__global__ void cvt_bf16(const float* __restrict__ in, __nv_bfloat16* __restrict__ out, int n)
{
    int i = blockIdx.x * blockDim.x + threadIdx.x;
    if (i < n) out[i] = __float2bfloat16(in[i]);
}

// ---------------- softmax bf16 in-place ----------------
__global__ void __launch_bounds__(256)
softmax_b16(__nv_bfloat16* __restrict__ data, int rowlen)
{
    __nv_bfloat16* p = data + (long long)blockIdx.x * rowlen;
    const int tid = threadIdx.x;
    __shared__ float red[8];

    float v[25];
    float mx = -3.0e38f;
#pragma unroll
    for (int i = 0; i < 25; i++) {
        int idx = tid + (i << 8);
        v[i] = (idx < rowlen) ? __bfloat162float(p[idx]) : -3.0e38f;
        mx = fmaxf(mx, v[i]);
    }
#pragma unroll
    for (int o = 16; o; o >>= 1) mx = fmaxf(mx, __shfl_xor_sync(0xffffffffu, mx, o));
    if ((tid & 31) == 0) red[tid >> 5] = mx;
    __syncthreads();
    mx = red[0];
#pragma unroll
    for (int w = 1; w < 8; w++) mx = fmaxf(mx, red[w]);
    __syncthreads();

    float s = 0.f;
#pragma unroll
    for (int i = 0; i < 25; i++) { v[i] = __expf(v[i] - mx); s += v[i]; }
#pragma unroll
    for (int o = 16; o; o >>= 1) s += __shfl_xor_sync(0xffffffffu, s, o);
    if ((tid & 31) == 0) red[tid >> 5] = s;
    __syncthreads();
    s = 0.f;
#pragma unroll
    for (int w = 0; w < 8; w++) s += red[w];
    float inv = 1.f / s;
#pragma unroll
    for (int i = 0; i < 25; i++) {
        int idx = tid + (i << 8);
        if (idx < rowlen) p[idx] = __float2bfloat16(v[i] * inv);
    }
}

// ---------------- softmax fp32 in-place ----------------
__global__ void __launch_bounds__(256)
softmax_rows(float* __restrict__ data, int rowlen)
{
    float* p = data + (long long)blockIdx.x * rowlen;
    const int tid = threadIdx.x;
    __shared__ float red[8];

    float v[25];
    float mx = -3.0e38f;
#pragma unroll
    for (int i = 0; i < 25; i++) {
        int idx = tid + (i << 8);
        v[i] = (idx < rowlen) ? p[idx] : -3.0e38f;
        mx = fmaxf(mx, v[i]);
    }
#pragma unroll
    for (int o = 16; o; o >>= 1) mx = fmaxf(mx, __shfl_xor_sync(0xffffffffu, mx, o));
    if ((tid & 31) == 0) red[tid >> 5] = mx;
    __syncthreads();
    mx = red[0];
#pragma unroll
    for (int w = 1; w < 8; w++) mx = fmaxf(mx, red[w]);
    __syncthreads();

    float s = 0.f;
#pragma unroll
    for (int i = 0; i < 25; i++) { v[i] = __expf(v[i] - mx); s += v[i]; }
#pragma unroll
    for (int o = 16; o; o >>= 1) s += __shfl_xor_sync(0xffffffffu, s, o);
    if ((tid & 31) == 0) red[tid >> 5] = s;
    __syncthreads();
    s = 0.f;
#pragma unroll
    for (int w = 0; w < 8; w++) s += red[w];
    float inv = 1.f / s;
#pragma unroll
    for (int i = 0; i < 25; i++) {
        int idx = tid + (i << 8);
        if (idx < rowlen) p[idx] = v[i] * inv;
    }
}

// ---------------- BN stats ----------------
__global__ void __launch_bounds__(256)
bn_stats(const float* __restrict__ wz, const float* __restrict__ bn_w,
         const float* __restrict__ bn_b, float* __restrict__ scale,
         float* __restrict__ shift)
{
    int c = blockIdx.x;
    int tid = threadIdx.x;
    float s = 0.f, sq = 0.f;
    for (int i = tid; i < NB * THW; i += 256) {
        int n = i / THW, t = i - n * THW;
        float v = wz[(long long)n * CT + (long long)c * THW + t];
        s += v;
        sq = fmaf(v, v, sq);
    }
    __shared__ float r1[8], r2[8];
#pragma unroll
    for (int o = 16; o; o >>= 1) {
        s  += __shfl_xor_sync(0xffffffffu, s,  o);
        sq += __shfl_xor_sync(0xffffffffu, sq, o);
    }
    if ((tid & 31) == 0) { r1[tid >> 5] = s; r2[tid >> 5] = sq; }
    __syncthreads();
    if (tid == 0) {
        s = 0.f; sq = 0.f;
#pragma unroll
        for (int w = 0; w < 8; w++) { s += r1[w]; sq += r2[w]; }
        const float invn = 1.f / (float)(NB * THW);
        float mu  = s * invn;
        float var = sq * invn - mu * mu;
        float sc  = bn_w[c] * rsqrtf(var + 1e-5f);
        scale[c] = sc;
        shift[c] = bn_b[c] - mu * sc;
    }
}

// ---------------- final combine ----------------
__global__ void final_k(const __nv_bfloat16* __restrict__ pm, const float* __restrict__ ma,
                        const float* __restrict__ wz, const float* __restrict__ scale,
                        const float* __restrict__ shift, const float* __restrict__ gamma,
                        float* __restrict__ out)
{
    long long i = (long long)blockIdx.x * blockDim.x + threadIdx.x;
    if (i >= (long long)NB * CT) return;
    int c = (int)((i / THW) % CC);
    out[i] = gamma[0] * __bfloat162float(pm[i]) * ma[i] + fmaf(wz[i], scale[c], shift[c]);
}

// ---------------- launch ----------------
extern "C" void kernel_launch(void* const* d_in, const int* in_sizes, int n_in,
                              void* d_out, int out_size)
{
    const float* x    = (const float*)d_in[0];
    const float* mask = (const float*)d_in[1];
    const float* Wh   = (const float*)d_in[2];
    const float* bh   = (const float*)d_in[3];
    const float* Wg   = (const float*)d_in[4];
    const float* bg   = (const float*)d_in[5];
    const float* Wm   = (const float*)d_in[6];
    const float* bm   = (const float*)d_in[7];
    const float* Wz   = (const float*)d_in[8];
    const float* bz   = (const float*)d_in[9];
    const float* bn_w = (const float*)d_in[10];
    const float* bn_b = (const float*)d_in[11];
    const float* gamma= (const float*)d_in[12];
    float* out = (float*)d_out;

    float *wz, *me, *scale, *shift;
    __nv_bfloat16 *att, *x3, *Wz3, *maskT, *Wb, *phxT, *pgT, *phm, *pm;
    cudaGetSymbolAddress((void**)&wz,     g_wz);
    cudaGetSymbolAddress((void**)&me,     g_me);
    cudaGetSymbolAddress((void**)&att,    g_att);
    cudaGetSymbolAddress((void**)&x3,     g_x3);
    cudaGetSymbolAddress((void**)&Wz3,    g_Wz3);
    cudaGetSymbolAddress((void**)&maskT,  g_maskT);
    cudaGetSymbolAddress((void**)&Wb,     g_Wb);
    cudaGetSymbolAddress((void**)&phxT,   g_phxT);
    cudaGetSymbolAddress((void**)&pgT,    g_pgT);
    cudaGetSymbolAddress((void**)&phm,    g_phm);
    cudaGetSymbolAddress((void**)&pm,     g_pm);
    cudaGetSymbolAddress((void**)&scale,  g_scale);
    cudaGetSymbolAddress((void**)&shift,  g_shift);

    const long long EE = (long long)EEL;
    const long long sX3 = (long long)THW * K3;
    const int SMEM_GEMM = STAGES * 32768;   // 96KB
    cudaFuncSetAttribute(gemm_bf16_mma, cudaFuncAttributeMaxDynamicSharedMemorySize, SMEM_GEMM);

    const dim3 t32(32, 8);

    // weight conversions / splits
    cvt_bf16<<<(CC * CC + 255) / 256, 256>>>(Wh, Wb + 0 * CC * CC, CC * CC);
    cvt_bf16<<<(CC * CC + 255) / 256, 256>>>(Wg, Wb + 1 * CC * CC, CC * CC);
    cvt_bf16<<<(CC * CC + 255) / 256, 256>>>(Wm, Wb + 2 * CC * CC, CC * CC);
    split_w<<<(CC * CC + 255) / 256, 256>>>(Wz, Wz3);

    // x -> x3 (transposed hi/lo split); mask -> maskT (bf16)
    split_x<<<dim3(THW / 32, CC / 32, NB), t32>>>(x, x3, CT, sX3);
    transpose_cvt<<<dim3(THW / 32, CC / 32, NB), t32>>>(mask, maskT, CC, THW, CT, CT);

    // projections on tensor cores (bf16 out); x hi-part read via ldB/ldA = K3
    // phxT[t,o] = sum_c x3[t,c]*Wh[o,c] + bh[o]
    gemm_bf16_mma<<<dim3(CC / 128, THW / 128, NB), 256, SMEM_GEMM>>>(
        x3, Wb + 0 * CC * CC, phxT, 1, nullptr, bh, THW, CC, CC, K3, CC, sX3, 0, CT);
    gemm_bf16_mma<<<dim3(CC / 128, THW / 128, NB), 256, SMEM_GEMM>>>(
        x3, Wb + 1 * CC * CC, pgT, 1, nullptr, bg, THW, CC, CC, K3, CC, sX3, 0, CT);
    // phm[o,s] = sum_c Wh[o,c]*maskT[s,c] + bh[o]
    gemm_bf16_mma<<<dim3(THW / 128, CC / 128, NB), 256, SMEM_GEMM>>>(
        Wb + 0 * CC * CC, maskT, phm, 1, bh, nullptr, CC, THW, CC, CC, CC, 0, CT, CT);
    // pm[o,t] = sum_c Wm[o,c]*x3[t,c] + bm[o]
    gemm_bf16_mma<<<dim3(THW / 128, CC / 128, NB), 256, SMEM_GEMM>>>(
        Wb + 2 * CC * CC, x3, pm, 1, bm, nullptr, CC, THW, CC, CC, K3, 0, sX3, CT);

    // wz[o,t] (near-fp32 via bf16x3 split, K=1536)
    gemm_bf16_mma<<<dim3(THW / 128, CC / 128, NB), 256, SMEM_GEMM>>>(
        Wz3, x3, wz, 0, bz, nullptr, CC, THW, K3, K3, K3, 0, sX3, CT);

    // energy[t,s] = sum_c phxT[t,c]*pgT[s,c]  -> bf16 directly into att buffer
    gemm_bf16_mma<<<dim3(THW / 128, THW / 128, NB), 256, SMEM_GEMM>>>(
        phxT, pgT, att, 1, nullptr, nullptr, THW, THW, CC, CC, CC, CT, CT, EE);

    // attention = softmax_s(energy), bf16 in place
    softmax_b16<<<NB * THW, 256>>>(att, THW);

    // mask_energy[c,t] = sum_s phm[c,s]*att[t,s]   (fp32 out)
    gemm_bf16_mma<<<dim3(THW / 128, CC / 128, NB), 256, SMEM_GEMM>>>(
        phm, att, me, 0, nullptr, nullptr, CC, THW, THW, THW, THW, CT, EE, CT);

    // mask_atten = softmax_t(mask_energy), in place
    softmax_rows<<<NB * CC, 256>>>(me, THW);

    // BN stats on wz
    bn_stats<<<CC, 256>>>(wz, bn_w, bn_b, scale, shift);

    // out = gamma*pm*mask_atten + BN(wz)
    final_k<<<(NB * CT + 255) / 256, 256>>>(pm, me, wz, scale, shift, gamma, out);
}